// round 8
// baseline (speedup 1.0000x reference)
#include <cuda_runtime.h>
#include <cuda_fp16.h>
#include <cstdint>
#include <math.h>

#define B_     32
#define CIN    128
#define H_     112
#define W_     112
#define COUT   256
#define E_     4
#define HOUT   56
#define WOUT   56
#define RTAPS  (CIN*9)          // 1152
#define HP     114              // padded H/W

// ---------------- scratch (device globals) ----------------
__device__ __align__(256) float  g_rw[B_ * E_];
__device__ __align__(256) float  g_rowsum[(size_t)B_ * H_ * CIN];
__device__ __align__(256) __half g_xp[(size_t)B_ * HP * HP * CIN];   // padded NHWC fp16
__device__ __align__(256) __half g_wh[(size_t)B_ * COUT * RTAPS];    // [b][oc][t*128+ic]

// ---------------- PTX helpers ----------------
__device__ __forceinline__ uint32_t smem_u32(const void* p) {
    uint32_t a;
    asm("{ .reg .u64 t; cvta.to.shared.u64 t, %1; cvt.u32.u64 %0, t; }" : "=r"(a) : "l"(p));
    return a;
}
#define CPASYNC16(dst, src) \
    asm volatile("cp.async.cg.shared.global [%0], [%1], 16;" \
                 :: "r"(dst), "l"(src) : "memory")
#define CPCOMMIT() asm volatile("cp.async.commit_group;" ::: "memory")
#define CPWAIT1()  asm volatile("cp.async.wait_group 1;" ::: "memory")
#define CPWAIT0()  asm volatile("cp.async.wait_group 0;" ::: "memory")

#define LDSM_X4(r0, r1, r2, r3, addr) \
    asm volatile("ldmatrix.sync.aligned.m8n8.x4.shared.b16 {%0,%1,%2,%3}, [%4];" \
                 : "=r"(r0), "=r"(r1), "=r"(r2), "=r"(r3) : "r"(addr))
#define LDSM_X2(r0, r1, addr) \
    asm volatile("ldmatrix.sync.aligned.m8n8.x2.shared.b16 {%0,%1}, [%2];" \
                 : "=r"(r0), "=r"(r1) : "r"(addr))

#define MMA16816(d, a, b0, b1) \
    asm volatile("mma.sync.aligned.m16n8k16.row.col.f32.f16.f16.f32 " \
                 "{%0,%1,%2,%3}, {%4,%5,%6,%7}, {%8,%9}, {%0,%1,%2,%3};" \
                 : "+f"((d)[0]), "+f"((d)[1]), "+f"((d)[2]), "+f"((d)[3]) \
                 : "r"((a)[0]), "r"((a)[1]), "r"((a)[2]), "r"((a)[3]), \
                   "r"(b0), "r"(b1))

__device__ __forceinline__ uint32_t sw128(uint32_t off) {
    return off ^ ((off >> 3) & 0x70);
}

// ---------------------------------------------------------------------------
// 0) Zero the halo border of the padded input
// ---------------------------------------------------------------------------
__global__ __launch_bounds__(256) void zero_border_kernel(__half* __restrict__ xp) {
    int i = blockIdx.x * 256 + threadIdx.x;
    if (i >= B_ * 452 * 16) return;
    int q = i & 15;
    int s = (i >> 4) % 452;
    int b = i / (452 * 16);
    int row, col;
    if (s < 114)      { row = 0;        col = s; }
    else if (s < 228) { row = 113;      col = s - 114; }
    else if (s < 340) { row = s - 227;  col = 0; }
    else              { row = s - 339;  col = 113; }
    size_t off = ((((size_t)b * HP + row) * HP) + col) * CIN + q * 8;
    *(uint4*)(xp + off) = make_uint4(0, 0, 0, 0);
}

// ---------------------------------------------------------------------------
// 1) NCHW fp32 -> padded NHWC fp16, fused per-row partial pooling sums.
// ---------------------------------------------------------------------------
__global__ __launch_bounds__(256) void split_x_kernel(const float* __restrict__ x,
                                                      __half* __restrict__ xp,
                                                      float* __restrict__ rowsum) {
    __shared__ float tile[64][113];
    int tid = threadIdx.x;
    int half = blockIdx.x & 1;
    int bh = blockIdx.x >> 1;
    int b = bh / H_, ih = bh % H_;
    int ic0 = half * 64;

    const float* src = x + (((size_t)b * CIN + ic0) * H_ + ih) * W_;
    for (int idx = tid; idx < 64 * W_; idx += 256) {
        int ic = idx / W_, iw = idx % W_;
        tile[ic][iw] = src[(size_t)ic * (H_ * W_) + iw];
    }
    __syncthreads();
    if (tid < 64) {
        float s = 0.f;
        #pragma unroll 4
        for (int iw = 0; iw < W_; iw++) s += tile[tid][iw];
        rowsum[((size_t)b * H_ + ih) * CIN + ic0 + tid] = s;
    }
    size_t obase = (((size_t)b * HP + (ih + 1)) * HP + 1) * CIN + ic0;
    for (int idx = tid; idx < W_ * 64; idx += 256) {
        int iw = idx >> 6, ic = idx & 63;
        xp[obase + (size_t)iw * CIN + ic] = __float2half_rn(tile[ic][iw]);
    }
}

// ---------------------------------------------------------------------------
// 1b) Fused pool-reduce + routing: one block per b.
// ---------------------------------------------------------------------------
__global__ __launch_bounds__(128) void pool_route_kernel(const float* __restrict__ rowsum,
                                                         const float* __restrict__ rw_w,
                                                         const float* __restrict__ rw_b,
                                                         float* __restrict__ rw) {
    __shared__ float pooled[CIN];
    int b = blockIdx.x, ic = threadIdx.x;
    float s = 0.f;
    const float* rs = rowsum + (size_t)b * H_ * CIN + ic;
    #pragma unroll 4
    for (int ih = 0; ih < H_; ih++) s += rs[(size_t)ih * CIN];
    pooled[ic] = s * (1.0f / (H_ * W_));
    __syncthreads();

    int wid = ic >> 5, lane = ic & 31;
    float z = 0.f;
    const float* ww = rw_w + wid * CIN;
    #pragma unroll
    for (int k = lane; k < CIN; k += 32) z += pooled[k] * ww[k];
    #pragma unroll
    for (int off = 16; off > 0; off >>= 1)
        z += __shfl_xor_sync(0xFFFFFFFFu, z, off);
    if (lane == 0)
        rw[b * E_ + wid] = 1.0f / (1.0f + expf(-(z + rw_b[wid])));
}

// ---------------------------------------------------------------------------
// 2) Mix expert weights -> per-sample fp16. Block = (oc, b-group of 4).
// ---------------------------------------------------------------------------
#define BGRP 4
__global__ __launch_bounds__(128) void combine_kernel(const float* __restrict__ ew,
                                                      const float* __restrict__ rw,
                                                      __half* __restrict__ wh) {
    __shared__ float srw[B_ * E_];
    int oc = blockIdx.x;
    int bg = blockIdx.y * BGRP;
    int ic = threadIdx.x;
    srw[ic] = rw[ic];
    __syncthreads();

    float w[E_][9];
    #pragma unroll
    for (int e = 0; e < E_; e++) {
        const float* p = ew + (((size_t)e * COUT + oc) * CIN + ic) * 9;
        #pragma unroll
        for (int t = 0; t < 9; t++) w[e][t] = p[t];
    }

    #pragma unroll 1
    for (int bi = 0; bi < BGRP; bi++) {
        int b = bg + bi;
        float r0 = srw[b * 4 + 0], r1 = srw[b * 4 + 1];
        float r2 = srw[b * 4 + 2], r3 = srw[b * 4 + 3];
        size_t ob = ((size_t)b * COUT + oc) * RTAPS + ic;
        #pragma unroll
        for (int t = 0; t < 9; t++) {
            float v = w[0][t] * r0 + w[1][t] * r1 + w[2][t] * r2 + w[3][t] * r3;
            wh[ob + (size_t)t * 128] = __float2half_rn(v);
        }
    }
}

// ---------------------------------------------------------------------------
// 3) Implicit-GEMM conv. Block: 512 threads / 16 warps, tile 128oc x 224n
//    (4 output rows). 3-stage cp.async, 1 sync/chunk, halo-padded loads.
//    Halves A-tile L2 traffic vs BN=112.
// ---------------------------------------------------------------------------
#define NROWS       4
#define BN          (NROWS * WOUT)        // 224
#define A_BYTES     16384                 // 128 x 64 fp16
#define BB_BYTES    (BN * 64 * 2)         // 28672
#define STAGE_BYTES (A_BYTES + BB_BYTES)  // 45056
#define NSTAGE      3
#define SM_TOTAL    (NSTAGE * STAGE_BYTES)  // 135168

__global__ __launch_bounds__(512, 1) void conv_mma_kernel(const __half* __restrict__ xp,
                                                          const __half* __restrict__ wgt,
                                                          float* __restrict__ out) {
    extern __shared__ char sm[];
    uint32_t smb = smem_u32(sm);
    int tid = threadIdx.x, lane = tid & 31, wid = tid >> 5;
    int wm = wid & 3, wn = wid >> 2;      // wm: 32-oc group; wn: output row
    int oh0 = blockIdx.x * NROWS;
    int ocb = blockIdx.y, b = blockIdx.z;

    const __half* wbase = wgt + ((size_t)b * COUT + ocb * 128) * RTAPS;
    const __half* xb = xp + (size_t)b * (HP * HP) * CIN;

    // ---- loader addresses (512 threads) ----
    const __half* srcA[2];
    uint32_t dstA[2];
    #pragma unroll
    for (int rep = 0; rep < 2; rep++) {
        int idx = tid + rep * 512;
        int row = idx >> 3, seg = idx & 7;
        srcA[rep] = wbase + (size_t)row * RTAPS + seg * 8;
        dstA[rep] = sw128((uint32_t)(idx * 16));
    }
    const __half* srcB[4];
    uint32_t dstB[4];
    #pragma unroll
    for (int rep = 0; rep < 4; rep++) {
        int idx = tid + rep * 512;
        if (idx < BN * 8) {
            int n = idx >> 3, seg = idx & 7;
            int p = n / WOUT;
            int ow = n - WOUT * p;
            srcB[rep] = xb + ((size_t)(2 * (oh0 + p)) * HP + 2 * ow) * CIN + seg * 8;
            dstB[rep] = A_BYTES + sw128((uint32_t)(idx * 16));
        }
    }
    bool b3 = (tid < BN * 8 - 3 * 512);   // idx 1536..1791 -> tid < 256

    float acc[2][7][4];
    #pragma unroll
    for (int mt = 0; mt < 2; mt++)
        #pragma unroll
        for (int nt = 0; nt < 7; nt++)
            #pragma unroll
            for (int q = 0; q < 4; q++) acc[mt][nt][q] = 0.f;

    auto issue_chunk = [&](int c, int stage) {
        uint32_t sa = smb + stage * STAGE_BYTES;
        int t = c >> 1, h = c & 1;
        int dy = t / 3, dx = t - 3 * dy;
        int boff = (dy * HP + dx) * CIN + h * 64;
        int aoff = c * 64;
        #pragma unroll
        for (int rep = 0; rep < 2; rep++)
            CPASYNC16(sa + dstA[rep], srcA[rep] + aoff);
        #pragma unroll
        for (int rep = 0; rep < 3; rep++)
            CPASYNC16(sa + dstB[rep], srcB[rep] + boff);
        if (b3) CPASYNC16(sa + dstB[3], srcB[3] + boff);
    };

    issue_chunk(0, 0); CPCOMMIT();
    issue_chunk(1, 1); CPCOMMIT();

    int arow = wm * 32 + (lane & 15);
    int akk0 = (lane >> 4) << 3;
    int bn0 = wn * 56 + (lane & 7) + ((lane >> 4) << 3);
    int bn6 = wn * 56 + 48 + (lane & 7);
    int bkk0 = ((lane >> 3) & 1) << 3;

    int st = 0, st2 = 2;
    for (int c = 0; c < 18; c++) {
        if (c < 17) { CPWAIT1(); } else { CPWAIT0(); }
        __syncthreads();

        if (c + 2 < 18) { issue_chunk(c + 2, st2); CPCOMMIT(); }

        uint32_t sa = smb + st * STAGE_BYTES;
        uint32_t sb = sa + A_BYTES;

        #pragma unroll
        for (int ks = 0; ks < 4; ks++) {
            int k0 = ks * 16;
            uint32_t afr[2][4];
            #pragma unroll
            for (int mt = 0; mt < 2; mt++)
                LDSM_X4(afr[mt][0], afr[mt][1], afr[mt][2], afr[mt][3],
                        sa + sw128((uint32_t)((arow + mt * 16) * 128 + (k0 + akk0) * 2)));
            uint32_t bfr[7][2];
            #pragma unroll
            for (int j = 0; j < 3; j++)
                LDSM_X4(bfr[2 * j][0], bfr[2 * j][1],
                        bfr[2 * j + 1][0], bfr[2 * j + 1][1],
                        sb + sw128((uint32_t)((bn0 + j * 16) * 128 + (k0 + bkk0) * 2)));
            LDSM_X2(bfr[6][0], bfr[6][1],
                    sb + sw128((uint32_t)(bn6 * 128 + (k0 + bkk0) * 2)));
            #pragma unroll
            for (int mt = 0; mt < 2; mt++)
                #pragma unroll
                for (int nt = 0; nt < 7; nt++)
                    MMA16816(acc[mt][nt], afr[mt], bfr[nt][0], bfr[nt][1]);
        }

        st = (st == NSTAGE - 1) ? 0 : st + 1;
        st2 = (st2 == NSTAGE - 1) ? 0 : st2 + 1;
    }

    // ---- epilogue: warp (wm, wn) writes row oh0+wn, oc wm*32..+32 ----
    int r = lane >> 2;
    int cb = (lane & 3) * 2;
    int oh = oh0 + wn;
    #pragma unroll
    for (int mt = 0; mt < 2; mt++) {
        int oc = ocb * 128 + wm * 32 + mt * 16 + r;
        #pragma unroll
        for (int nt = 0; nt < 7; nt++) {
            int ow = nt * 8 + cb;
            float* op = out + (((size_t)b * COUT + oc) * HOUT + oh) * WOUT + ow;
            *(float2*)op = make_float2(acc[mt][nt][0], acc[mt][nt][1]);
            *(float2*)(op + (size_t)8 * HOUT * WOUT) =
                make_float2(acc[mt][nt][2], acc[mt][nt][3]);   // oc + 8
        }
    }
}

// ---------------------------------------------------------------------------
extern "C" void kernel_launch(void* const* d_in, const int* in_sizes, int n_in,
                              void* d_out, int out_size) {
    const float* x    = (const float*)d_in[0];
    const float* rw_w = (const float*)d_in[1];
    const float* rw_b = (const float*)d_in[2];
    const float* ew   = (const float*)d_in[3];
    float* out = (float*)d_out;

    float *rw, *rowsum;
    __half *xpd, *wh;
    cudaGetSymbolAddress((void**)&rw, g_rw);
    cudaGetSymbolAddress((void**)&rowsum, g_rowsum);
    cudaGetSymbolAddress((void**)&xpd, g_xp);
    cudaGetSymbolAddress((void**)&wh, g_wh);

    zero_border_kernel<<<(B_ * 452 * 16 + 255) / 256, 256>>>(xpd);
    split_x_kernel<<<B_ * H_ * 2, 256>>>(x, xpd, rowsum);
    pool_route_kernel<<<B_, 128>>>(rowsum, rw_w, rw_b, rw);
    combine_kernel<<<dim3(COUT, B_ / BGRP), CIN>>>(ew, rw, wh);

    cudaFuncSetAttribute(conv_mma_kernel,
                         cudaFuncAttributeMaxDynamicSharedMemorySize, SM_TOTAL);
    conv_mma_kernel<<<dim3(HOUT / NROWS, 2, B_), 512, SM_TOTAL>>>(xpd, wh, out);
}

// round 9
// speedup vs baseline: 1.0443x; 1.0443x over previous
#include <cuda_runtime.h>
#include <cuda_fp16.h>
#include <cstdint>
#include <math.h>

#define B_     32
#define CIN    128
#define H_     112
#define W_     112
#define COUT   256
#define E_     4
#define HOUT   56
#define WOUT   56
#define RTAPS  (CIN*9)          // 1152

// ---------------- scratch (device globals) ----------------
__device__ __align__(256) float  g_rw[B_ * E_];
__device__ __align__(256) float  g_rowsum[(size_t)B_ * H_ * CIN];
__device__ __align__(256) __half g_xh[(size_t)B_ * H_ * W_ * CIN];   // NHWC fp16
__device__ __align__(256) __half g_wh[(size_t)B_ * COUT * RTAPS];    // [b][oc][t*128+ic]

// ---------------- PTX helpers ----------------
__device__ __forceinline__ uint32_t smem_u32(const void* p) {
    uint32_t a;
    asm("{ .reg .u64 t; cvta.to.shared.u64 t, %1; cvt.u32.u64 %0, t; }" : "=r"(a) : "l"(p));
    return a;
}
#define CPASYNC(dst, src, sz) \
    asm volatile("cp.async.cg.shared.global [%0], [%1], 16, %2;" \
                 :: "r"(dst), "l"(src), "r"(sz) : "memory")
#define CPCOMMIT() asm volatile("cp.async.commit_group;" ::: "memory")
#define CPWAIT1()  asm volatile("cp.async.wait_group 1;" ::: "memory")
#define CPWAIT0()  asm volatile("cp.async.wait_group 0;" ::: "memory")

#define LDSM_X4(r0, r1, r2, r3, addr) \
    asm volatile("ldmatrix.sync.aligned.m8n8.x4.shared.b16 {%0,%1,%2,%3}, [%4];" \
                 : "=r"(r0), "=r"(r1), "=r"(r2), "=r"(r3) : "r"(addr))
#define LDSM_X2(r0, r1, addr) \
    asm volatile("ldmatrix.sync.aligned.m8n8.x2.shared.b16 {%0,%1}, [%2];" \
                 : "=r"(r0), "=r"(r1) : "r"(addr))

#define MMA16816(d, a, b0, b1) \
    asm volatile("mma.sync.aligned.m16n8k16.row.col.f32.f16.f16.f32 " \
                 "{%0,%1,%2,%3}, {%4,%5,%6,%7}, {%8,%9}, {%0,%1,%2,%3};" \
                 : "+f"((d)[0]), "+f"((d)[1]), "+f"((d)[2]), "+f"((d)[3]) \
                 : "r"((a)[0]), "r"((a)[1]), "r"((a)[2]), "r"((a)[3]), \
                   "r"(b0), "r"(b1))

__device__ __forceinline__ uint32_t sw128(uint32_t off) {
    return off ^ ((off >> 3) & 0x70);
}

// ---------------------------------------------------------------------------
// 1) NCHW fp32 -> NHWC fp16, fused per-row partial pooling sums.
// ---------------------------------------------------------------------------
__global__ __launch_bounds__(256) void split_x_kernel(const float* __restrict__ x,
                                                      __half* __restrict__ xh,
                                                      float* __restrict__ rowsum) {
    __shared__ float tile[64][113];
    int tid = threadIdx.x;
    int half = blockIdx.x & 1;
    int bh = blockIdx.x >> 1;
    int b = bh / H_, ih = bh % H_;
    int ic0 = half * 64;

    const float* src = x + (((size_t)b * CIN + ic0) * H_ + ih) * W_;
    for (int idx = tid; idx < 64 * W_; idx += 256) {
        int ic = idx / W_, iw = idx % W_;
        tile[ic][iw] = src[(size_t)ic * (H_ * W_) + iw];
    }
    __syncthreads();
    if (tid < 64) {
        float s = 0.f;
        #pragma unroll 4
        for (int iw = 0; iw < W_; iw++) s += tile[tid][iw];
        rowsum[((size_t)b * H_ + ih) * CIN + ic0 + tid] = s;
    }
    size_t obase = (((size_t)b * H_ + ih) * W_) * CIN + ic0;
    for (int idx = tid; idx < W_ * 64; idx += 256) {
        int iw = idx >> 6, ic = idx & 63;
        xh[obase + (size_t)iw * CIN + ic] = __float2half_rn(tile[ic][iw]);
    }
}

// ---------------------------------------------------------------------------
// 1b) Fused pool-reduce + routing: one block per b (replaces the serial
//     grid=1 routing kernel that cost 9.4us).
// ---------------------------------------------------------------------------
__global__ __launch_bounds__(128) void pool_route_kernel(const float* __restrict__ rowsum,
                                                         const float* __restrict__ rw_w,
                                                         const float* __restrict__ rw_b,
                                                         float* __restrict__ rw) {
    __shared__ float pooled[CIN];
    int b = blockIdx.x, ic = threadIdx.x;
    float s = 0.f;
    const float* rs = rowsum + (size_t)b * H_ * CIN + ic;
    #pragma unroll 4
    for (int ih = 0; ih < H_; ih++) s += rs[(size_t)ih * CIN];
    pooled[ic] = s * (1.0f / (H_ * W_));
    __syncthreads();

    int wid = ic >> 5, lane = ic & 31;
    float z = 0.f;
    const float* ww = rw_w + wid * CIN;
    #pragma unroll
    for (int k = lane; k < CIN; k += 32) z += pooled[k] * ww[k];
    #pragma unroll
    for (int off = 16; off > 0; off >>= 1)
        z += __shfl_xor_sync(0xFFFFFFFFu, z, off);
    if (lane == 0)
        rw[b * E_ + wid] = 1.0f / (1.0f + expf(-(z + rw_b[wid])));
}

// ---------------------------------------------------------------------------
// 2) Mix expert weights -> per-sample fp16. Block = (oc, b-group of 8).
// ---------------------------------------------------------------------------
#define BGRP 8
__global__ __launch_bounds__(128) void combine_kernel(const float* __restrict__ ew,
                                                      const float* __restrict__ rw,
                                                      __half* __restrict__ wh) {
    __shared__ float srw[B_ * E_];
    int oc = blockIdx.x;
    int bg = blockIdx.y * BGRP;
    int ic = threadIdx.x;
    srw[ic] = rw[ic];
    __syncthreads();

    float w[E_][9];
    #pragma unroll
    for (int e = 0; e < E_; e++) {
        const float* p = ew + (((size_t)e * COUT + oc) * CIN + ic) * 9;
        #pragma unroll
        for (int t = 0; t < 9; t++) w[e][t] = p[t];
    }

    #pragma unroll 1
    for (int bi = 0; bi < BGRP; bi++) {
        int b = bg + bi;
        float r0 = srw[b * 4 + 0], r1 = srw[b * 4 + 1];
        float r2 = srw[b * 4 + 2], r3 = srw[b * 4 + 3];
        size_t ob = ((size_t)b * COUT + oc) * RTAPS + ic;
        #pragma unroll
        for (int t = 0; t < 9; t++) {
            float v = w[0][t] * r0 + w[1][t] * r1 + w[2][t] * r2 + w[3][t] * r3;
            wh[ob + (size_t)t * 128] = __float2half_rn(v);
        }
    }
}

// ---------------------------------------------------------------------------
// 3) Implicit-GEMM conv via mma.sync. Block: (b, 128 oc, 2 out rows, N=112).
//    256 threads, 8 warps. 3-stage cp.async pipeline, 1 sync per chunk.
//    (Byte-identical to the 244.3us R5 version.)
// ---------------------------------------------------------------------------
#define A_BYTES     16384                 // 128 x 64 fp16
#define BB_BYTES    14336                 // 112 x 64 fp16
#define STAGE_BYTES (A_BYTES + BB_BYTES)  // 30720
#define NSTAGE      3
#define SM_TOTAL    (NSTAGE * STAGE_BYTES)  // 92160

__device__ __forceinline__ void load_chunk(int c, uint32_t smb, int stage,
                                           const __half* __restrict__ wbase,
                                           const __half* __restrict__ xb,
                                           int oh0, int tid) {
    int t = c >> 1, h = c & 1;
    int dy = t / 3, dx = t - 3 * dy;
    uint32_t sa = smb + stage * STAGE_BYTES;
    uint32_t sb = sa + A_BYTES;

    // A: 128 rows (oc) x 64 k, SW128
    const __half* wp = wbase + t * 128 + h * 64;
    #pragma unroll
    for (int rep = 0; rep < 4; rep++) {
        int idx = tid + rep * 256;
        int row = idx >> 3, seg = idx & 7;
        const char* src = (const char*)(wp + (size_t)row * RTAPS) + seg * 16;
        CPASYNC(sa + sw128((uint32_t)(idx * 16)), src, 16);
    }
    // B: 112 rows (2 output rows x 56 cols) x 64 k, zero-filled OOB
    #pragma unroll
    for (int rep = 0; rep < 4; rep++) {
        int idx = tid + rep * 256;
        if (idx < 896) {
            int n = idx >> 3, seg = idx & 7;
            int p = (n >= 56) ? 1 : 0;
            int ow = n - 56 * p;
            int ih = 2 * (oh0 + p) - 1 + dy;
            int iw = 2 * ow - 1 + dx;
            bool ok = ((unsigned)ih < (unsigned)H_) && ((unsigned)iw < (unsigned)W_);
            const char* src = ok
                ? (const char*)(xb + ((size_t)ih * W_ + iw) * CIN + h * 64) + seg * 16
                : (const char*)xb;
            CPASYNC(sb + sw128((uint32_t)(idx * 16)), src, ok ? 16u : 0u);
        }
    }
}

__global__ __launch_bounds__(256, 2) void conv_mma_kernel(const __half* __restrict__ xh,
                                                          const __half* __restrict__ wgt,
                                                          float* __restrict__ out) {
    extern __shared__ char sm[];
    uint32_t smb = smem_u32(sm);
    int tid = threadIdx.x, lane = tid & 31, wid = tid >> 5;
    int wm = wid & 3, wn = wid >> 2;
    int oh0 = blockIdx.x * 2;
    int ocb = blockIdx.y, b = blockIdx.z;

    const __half* wbase = wgt + ((size_t)b * COUT + ocb * 128) * RTAPS;
    const __half* xb = xh + (size_t)b * (H_ * W_) * CIN;

    float acc[2][7][4];
    #pragma unroll
    for (int mt = 0; mt < 2; mt++)
        #pragma unroll
        for (int nt = 0; nt < 7; nt++)
            #pragma unroll
            for (int q = 0; q < 4; q++) acc[mt][nt][q] = 0.f;

    load_chunk(0, smb, 0, wbase, xb, oh0, tid);
    CPCOMMIT();
    load_chunk(1, smb, 1, wbase, xb, oh0, tid);
    CPCOMMIT();

    int st = 0;                       // stage of chunk c
    int st2 = 2;                      // stage for chunk c+2
    for (int c = 0; c < 18; c++) {
        if (c < 17) { CPWAIT1(); } else { CPWAIT0(); }
        __syncthreads();

        if (c + 2 < 18) {
            load_chunk(c + 2, smb, st2, wbase, xb, oh0, tid);
            CPCOMMIT();
        }

        uint32_t sa = smb + st * STAGE_BYTES;
        uint32_t sb = sa + A_BYTES;

        #pragma unroll
        for (int ks = 0; ks < 4; ks++) {
            int k0 = ks * 16;
            uint32_t afr[2][4];
            #pragma unroll
            for (int mt = 0; mt < 2; mt++) {
                int row = wm * 32 + mt * 16 + (lane & 15);
                int kk = k0 + ((lane >> 4) << 3);
                LDSM_X4(afr[mt][0], afr[mt][1], afr[mt][2], afr[mt][3],
                        sa + sw128((uint32_t)(row * 128 + kk * 2)));
            }
            uint32_t bfr[7][2];
            #pragma unroll
            for (int j = 0; j < 3; j++) {
                int n = wn * 56 + j * 16 + (lane & 7) + ((lane >> 4) << 3);
                int kk = k0 + (((lane >> 3) & 1) << 3);
                LDSM_X4(bfr[2 * j][0], bfr[2 * j][1], bfr[2 * j + 1][0], bfr[2 * j + 1][1],
                        sb + sw128((uint32_t)(n * 128 + kk * 2)));
            }
            {
                int n = wn * 56 + 48 + (lane & 7);
                int kk = k0 + (((lane >> 3) & 1) << 3);
                LDSM_X2(bfr[6][0], bfr[6][1],
                        sb + sw128((uint32_t)(n * 128 + kk * 2)));
            }
            #pragma unroll
            for (int mt = 0; mt < 2; mt++)
                #pragma unroll
                for (int nt = 0; nt < 7; nt++)
                    MMA16816(acc[mt][nt], afr[mt], bfr[nt][0], bfr[nt][1]);
        }

        st = (st == NSTAGE - 1) ? 0 : st + 1;
        st2 = (st2 == NSTAGE - 1) ? 0 : st2 + 1;
    }

    // ---- epilogue: warp (wm, wn) writes row oh0+wn, oc range wm*32..+32 ----
    int r = lane >> 2;
    int cb = (lane & 3) * 2;
    int oh = oh0 + wn;
    #pragma unroll
    for (int mt = 0; mt < 2; mt++) {
        int oc = ocb * 128 + wm * 32 + mt * 16 + r;
        #pragma unroll
        for (int nt = 0; nt < 7; nt++) {
            int ow = nt * 8 + cb;
            float* op = out + (((size_t)b * COUT + oc) * HOUT + oh) * WOUT + ow;
            *(float2*)op = make_float2(acc[mt][nt][0], acc[mt][nt][1]);
            *(float2*)(op + (size_t)8 * HOUT * WOUT) =
                make_float2(acc[mt][nt][2], acc[mt][nt][3]);   // oc + 8
        }
    }
}

// ---------------------------------------------------------------------------
extern "C" void kernel_launch(void* const* d_in, const int* in_sizes, int n_in,
                              void* d_out, int out_size) {
    const float* x    = (const float*)d_in[0];
    const float* rw_w = (const float*)d_in[1];
    const float* rw_b = (const float*)d_in[2];
    const float* ew   = (const float*)d_in[3];
    float* out = (float*)d_out;

    float *rw, *rowsum;
    __half *xh, *wh;
    cudaGetSymbolAddress((void**)&rw, g_rw);
    cudaGetSymbolAddress((void**)&rowsum, g_rowsum);
    cudaGetSymbolAddress((void**)&xh, g_xh);
    cudaGetSymbolAddress((void**)&wh, g_wh);

    split_x_kernel<<<B_ * H_ * 2, 256>>>(x, xh, rowsum);
    pool_route_kernel<<<B_, 128>>>(rowsum, rw_w, rw_b, rw);
    combine_kernel<<<dim3(COUT, B_ / BGRP), CIN>>>(ew, rw, wh);

    cudaFuncSetAttribute(conv_mma_kernel,
                         cudaFuncAttributeMaxDynamicSharedMemorySize, SM_TOTAL);
    conv_mma_kernel<<<dim3(HOUT / 2, 2, B_), 256, SM_TOTAL>>>(xh, wh, out);
}

// round 10
// speedup vs baseline: 1.1280x; 1.0802x over previous
#include <cuda_runtime.h>
#include <cuda_fp16.h>
#include <cstdint>
#include <math.h>

#define B_     32
#define CIN    128
#define H_     112
#define W_     112
#define COUT   256
#define E_     4
#define HOUT   56
#define WOUT   56
#define RTAPS  (CIN*9)          // 1152

// ---------------- scratch (device globals) ----------------
__device__ __align__(256) float  g_rw[B_ * E_];
__device__ __align__(256) float  g_rowsum[(size_t)B_ * H_ * CIN];
__device__ __align__(256) __half g_xh[(size_t)B_ * H_ * W_ * CIN];   // NHWC fp16
__device__ __align__(256) __half g_wh[(size_t)B_ * COUT * RTAPS];    // [b][oc][t*128+ic]

// ---------------- PTX helpers ----------------
__device__ __forceinline__ uint32_t smem_u32(const void* p) {
    uint32_t a;
    asm("{ .reg .u64 t; cvta.to.shared.u64 t, %1; cvt.u32.u64 %0, t; }" : "=r"(a) : "l"(p));
    return a;
}
#define CPASYNC(dst, src, sz) \
    asm volatile("cp.async.cg.shared.global [%0], [%1], 16, %2;" \
                 :: "r"(dst), "l"(src), "r"(sz) : "memory")
#define CPCOMMIT() asm volatile("cp.async.commit_group;" ::: "memory")
#define CPWAIT1()  asm volatile("cp.async.wait_group 1;" ::: "memory")
#define CPWAIT0()  asm volatile("cp.async.wait_group 0;" ::: "memory")

#define LDSM_X4(r0, r1, r2, r3, addr) \
    asm volatile("ldmatrix.sync.aligned.m8n8.x4.shared.b16 {%0,%1,%2,%3}, [%4];" \
                 : "=r"(r0), "=r"(r1), "=r"(r2), "=r"(r3) : "r"(addr))
#define LDSM_X2(r0, r1, addr) \
    asm volatile("ldmatrix.sync.aligned.m8n8.x2.shared.b16 {%0,%1}, [%2];" \
                 : "=r"(r0), "=r"(r1) : "r"(addr))

#define MMA16816(d, a, b0, b1) \
    asm volatile("mma.sync.aligned.m16n8k16.row.col.f32.f16.f16.f32 " \
                 "{%0,%1,%2,%3}, {%4,%5,%6,%7}, {%8,%9}, {%0,%1,%2,%3};" \
                 : "+f"((d)[0]), "+f"((d)[1]), "+f"((d)[2]), "+f"((d)[3]) \
                 : "r"((a)[0]), "r"((a)[1]), "r"((a)[2]), "r"((a)[3]), \
                   "r"(b0), "r"(b1))

__device__ __forceinline__ uint32_t sw128(uint32_t off) {
    return off ^ ((off >> 3) & 0x70);
}

// ---------------------------------------------------------------------------
// 1) NCHW fp32 -> NHWC fp16 transpose + per-row pooling sums.
//    One 512-thread block per (b, ih); full 128 ic; float4 reads, half2 writes.
// ---------------------------------------------------------------------------
#define TS 113                      // tile row stride (floats)
#define SPLIT_SMEM (CIN * TS * 4)   // 57856 bytes

__global__ __launch_bounds__(512) void split_x_kernel(const float* __restrict__ x,
                                                      __half* __restrict__ xh,
                                                      float* __restrict__ rowsum) {
    extern __shared__ float tile[];   // [128][113]
    int tid = threadIdx.x;
    int bh = blockIdx.x;
    int b = bh / H_, ih = bh % H_;

    // read: 128 ic x 28 float4 (3584 quads)
    const float* src = x + ((size_t)b * CIN) * (H_ * W_) + (size_t)ih * W_;
    #pragma unroll
    for (int rep = 0; rep < 7; rep++) {
        int i = tid + rep * 512;
        int ic = i / 28, q = i - ic * 28;
        float4 v = *(const float4*)(src + (size_t)ic * (H_ * W_) + q * 4);
        float* tp = &tile[ic * TS + q * 4];
        tp[0] = v.x; tp[1] = v.y; tp[2] = v.z; tp[3] = v.w;
    }
    __syncthreads();

    // rowsum: threads 0..127 each sum one ic row (concurrent with writes below)
    if (tid < CIN) {
        const float* tp = &tile[tid * TS];
        float s = 0.f;
        #pragma unroll 8
        for (int iw = 0; iw < W_; iw++) s += tp[iw];
        rowsum[((size_t)b * H_ + ih) * CIN + tid] = s;
    }

    // write: 112 iw x 64 half2 (7168), warp writes 128B contiguous
    size_t obase = (((size_t)b * H_ + ih) * W_) * CIN;
    #pragma unroll
    for (int rep = 0; rep < 14; rep++) {
        int i = tid + rep * 512;
        int iw = i >> 6, icp = i & 63;
        float v0 = tile[(2 * icp) * TS + iw];
        float v1 = tile[(2 * icp + 1) * TS + iw];
        *(__half2*)(xh + obase + (size_t)iw * CIN + icp * 2) =
            __floats2half2_rn(v0, v1);
    }
}

// ---------------------------------------------------------------------------
// 1b) Fused pool-reduce + routing: one block per b.
// ---------------------------------------------------------------------------
__global__ __launch_bounds__(128) void pool_route_kernel(const float* __restrict__ rowsum,
                                                         const float* __restrict__ rw_w,
                                                         const float* __restrict__ rw_b,
                                                         float* __restrict__ rw) {
    __shared__ float pooled[CIN];
    int b = blockIdx.x, ic = threadIdx.x;
    float s = 0.f;
    const float* rs = rowsum + (size_t)b * H_ * CIN + ic;
    #pragma unroll 4
    for (int ih = 0; ih < H_; ih++) s += rs[(size_t)ih * CIN];
    pooled[ic] = s * (1.0f / (H_ * W_));
    __syncthreads();

    int wid = ic >> 5, lane = ic & 31;
    float z = 0.f;
    const float* ww = rw_w + wid * CIN;
    #pragma unroll
    for (int k = lane; k < CIN; k += 32) z += pooled[k] * ww[k];
    #pragma unroll
    for (int off = 16; off > 0; off >>= 1)
        z += __shfl_xor_sync(0xFFFFFFFFu, z, off);
    if (lane == 0)
        rw[b * E_ + wid] = 1.0f / (1.0f + expf(-(z + rw_b[wid])));
}

// ---------------------------------------------------------------------------
// 2) Mix expert weights -> per-sample fp16. Block = (oc, b-group of 8).
// ---------------------------------------------------------------------------
#define BGRP 8
__global__ __launch_bounds__(128) void combine_kernel(const float* __restrict__ ew,
                                                      const float* __restrict__ rw,
                                                      __half* __restrict__ wh) {
    __shared__ float srw[B_ * E_];
    int oc = blockIdx.x;
    int bg = blockIdx.y * BGRP;
    int ic = threadIdx.x;
    srw[ic] = rw[ic];
    __syncthreads();

    float w[E_][9];
    #pragma unroll
    for (int e = 0; e < E_; e++) {
        const float* p = ew + (((size_t)e * COUT + oc) * CIN + ic) * 9;
        #pragma unroll
        for (int t = 0; t < 9; t++) w[e][t] = p[t];
    }

    #pragma unroll 1
    for (int bi = 0; bi < BGRP; bi++) {
        int b = bg + bi;
        float r0 = srw[b * 4 + 0], r1 = srw[b * 4 + 1];
        float r2 = srw[b * 4 + 2], r3 = srw[b * 4 + 3];
        size_t ob = ((size_t)b * COUT + oc) * RTAPS + ic;
        #pragma unroll
        for (int t = 0; t < 9; t++) {
            float v = w[0][t] * r0 + w[1][t] * r1 + w[2][t] * r2 + w[3][t] * r3;
            wh[ob + (size_t)t * 128] = __float2half_rn(v);
        }
    }
}

// ---------------------------------------------------------------------------
// 3) Implicit-GEMM conv via mma.sync. Block: (b, 128 oc, 2 out rows, N=112).
//    256 threads, 8 warps. 3-stage cp.async pipeline, 1 sync per chunk.
//    (Byte-identical to the proven R5/R9 version.)
// ---------------------------------------------------------------------------
#define A_BYTES     16384                 // 128 x 64 fp16
#define BB_BYTES    14336                 // 112 x 64 fp16
#define STAGE_BYTES (A_BYTES + BB_BYTES)  // 30720
#define NSTAGE      3
#define SM_TOTAL    (NSTAGE * STAGE_BYTES)  // 92160

__device__ __forceinline__ void load_chunk(int c, uint32_t smb, int stage,
                                           const __half* __restrict__ wbase,
                                           const __half* __restrict__ xb,
                                           int oh0, int tid) {
    int t = c >> 1, h = c & 1;
    int dy = t / 3, dx = t - 3 * dy;
    uint32_t sa = smb + stage * STAGE_BYTES;
    uint32_t sb = sa + A_BYTES;

    const __half* wp = wbase + t * 128 + h * 64;
    #pragma unroll
    for (int rep = 0; rep < 4; rep++) {
        int idx = tid + rep * 256;
        int row = idx >> 3, seg = idx & 7;
        const char* src = (const char*)(wp + (size_t)row * RTAPS) + seg * 16;
        CPASYNC(sa + sw128((uint32_t)(idx * 16)), src, 16);
    }
    #pragma unroll
    for (int rep = 0; rep < 4; rep++) {
        int idx = tid + rep * 256;
        if (idx < 896) {
            int n = idx >> 3, seg = idx & 7;
            int p = (n >= 56) ? 1 : 0;
            int ow = n - 56 * p;
            int ih = 2 * (oh0 + p) - 1 + dy;
            int iw = 2 * ow - 1 + dx;
            bool ok = ((unsigned)ih < (unsigned)H_) && ((unsigned)iw < (unsigned)W_);
            const char* src = ok
                ? (const char*)(xb + ((size_t)ih * W_ + iw) * CIN + h * 64) + seg * 16
                : (const char*)xb;
            CPASYNC(sb + sw128((uint32_t)(idx * 16)), src, ok ? 16u : 0u);
        }
    }
}

__global__ __launch_bounds__(256, 2) void conv_mma_kernel(const __half* __restrict__ xh,
                                                          const __half* __restrict__ wgt,
                                                          float* __restrict__ out) {
    extern __shared__ char sm[];
    uint32_t smb = smem_u32(sm);
    int tid = threadIdx.x, lane = tid & 31, wid = tid >> 5;
    int wm = wid & 3, wn = wid >> 2;
    int oh0 = blockIdx.x * 2;
    int ocb = blockIdx.y, b = blockIdx.z;

    const __half* wbase = wgt + ((size_t)b * COUT + ocb * 128) * RTAPS;
    const __half* xb = xh + (size_t)b * (H_ * W_) * CIN;

    float acc[2][7][4];
    #pragma unroll
    for (int mt = 0; mt < 2; mt++)
        #pragma unroll
        for (int nt = 0; nt < 7; nt++)
            #pragma unroll
            for (int q = 0; q < 4; q++) acc[mt][nt][q] = 0.f;

    load_chunk(0, smb, 0, wbase, xb, oh0, tid);
    CPCOMMIT();
    load_chunk(1, smb, 1, wbase, xb, oh0, tid);
    CPCOMMIT();

    int st = 0, st2 = 2;
    for (int c = 0; c < 18; c++) {
        if (c < 17) { CPWAIT1(); } else { CPWAIT0(); }
        __syncthreads();

        if (c + 2 < 18) {
            load_chunk(c + 2, smb, st2, wbase, xb, oh0, tid);
            CPCOMMIT();
        }

        uint32_t sa = smb + st * STAGE_BYTES;
        uint32_t sb = sa + A_BYTES;

        #pragma unroll
        for (int ks = 0; ks < 4; ks++) {
            int k0 = ks * 16;
            uint32_t afr[2][4];
            #pragma unroll
            for (int mt = 0; mt < 2; mt++) {
                int row = wm * 32 + mt * 16 + (lane & 15);
                int kk = k0 + ((lane >> 4) << 3);
                LDSM_X4(afr[mt][0], afr[mt][1], afr[mt][2], afr[mt][3],
                        sa + sw128((uint32_t)(row * 128 + kk * 2)));
            }
            uint32_t bfr[7][2];
            #pragma unroll
            for (int j = 0; j < 3; j++) {
                int n = wn * 56 + j * 16 + (lane & 7) + ((lane >> 4) << 3);
                int kk = k0 + (((lane >> 3) & 1) << 3);
                LDSM_X4(bfr[2 * j][0], bfr[2 * j][1], bfr[2 * j + 1][0], bfr[2 * j + 1][1],
                        sb + sw128((uint32_t)(n * 128 + kk * 2)));
            }
            {
                int n = wn * 56 + 48 + (lane & 7);
                int kk = k0 + (((lane >> 3) & 1) << 3);
                LDSM_X2(bfr[6][0], bfr[6][1],
                        sb + sw128((uint32_t)(n * 128 + kk * 2)));
            }
            #pragma unroll
            for (int mt = 0; mt < 2; mt++)
                #pragma unroll
                for (int nt = 0; nt < 7; nt++)
                    MMA16816(acc[mt][nt], afr[mt], bfr[nt][0], bfr[nt][1]);
        }

        st = (st == NSTAGE - 1) ? 0 : st + 1;
        st2 = (st2 == NSTAGE - 1) ? 0 : st2 + 1;
    }

    int r = lane >> 2;
    int cb = (lane & 3) * 2;
    int oh = oh0 + wn;
    #pragma unroll
    for (int mt = 0; mt < 2; mt++) {
        int oc = ocb * 128 + wm * 32 + mt * 16 + r;
        #pragma unroll
        for (int nt = 0; nt < 7; nt++) {
            int ow = nt * 8 + cb;
            float* op = out + (((size_t)b * COUT + oc) * HOUT + oh) * WOUT + ow;
            *(float2*)op = make_float2(acc[mt][nt][0], acc[mt][nt][1]);
            *(float2*)(op + (size_t)8 * HOUT * WOUT) =
                make_float2(acc[mt][nt][2], acc[mt][nt][3]);   // oc + 8
        }
    }
}

// ---------------------------------------------------------------------------
extern "C" void kernel_launch(void* const* d_in, const int* in_sizes, int n_in,
                              void* d_out, int out_size) {
    const float* x    = (const float*)d_in[0];
    const float* rw_w = (const float*)d_in[1];
    const float* rw_b = (const float*)d_in[2];
    const float* ew   = (const float*)d_in[3];
    float* out = (float*)d_out;

    float *rw, *rowsum;
    __half *xh, *wh;
    cudaGetSymbolAddress((void**)&rw, g_rw);
    cudaGetSymbolAddress((void**)&rowsum, g_rowsum);
    cudaGetSymbolAddress((void**)&xh, g_xh);
    cudaGetSymbolAddress((void**)&wh, g_wh);

    cudaFuncSetAttribute(split_x_kernel,
                         cudaFuncAttributeMaxDynamicSharedMemorySize, SPLIT_SMEM);
    split_x_kernel<<<B_ * H_, 512, SPLIT_SMEM>>>(x, xh, rowsum);
    pool_route_kernel<<<B_, 128>>>(rowsum, rw_w, rw_b, rw);
    combine_kernel<<<dim3(COUT, B_ / BGRP), CIN>>>(ew, rw, wh);

    cudaFuncSetAttribute(conv_mma_kernel,
                         cudaFuncAttributeMaxDynamicSharedMemorySize, SM_TOTAL);
    conv_mma_kernel<<<dim3(HOUT / 2, 2, B_), 256, SM_TOTAL>>>(xh, wh, out);
}